// round 14
// baseline (speedup 1.0000x reference)
#include <cuda_runtime.h>
#include <cfloat>
#include <stdint.h>

#define N_NODES 100000
#define N_EDGES 1600000
#define BGRAPH  64
#define DINP    9
#define H       128
#define EPS     1e-5f

#define POOL_CH  16
#define CAP      96     // bucket capacity; P(deg>=96) < 1e-40 for Poisson(16)

typedef unsigned u32;

// ---------------- scratch (device globals; no allocation allowed) -----------
// Interleaved bf16 hi/lo storage per node: 128 u32 words.
// word[2p] = hi pair p (ch 2p lo16, 2p+1 hi16); word[2p+1] = lo pair p.
__device__ u32 g_hA[N_NODES * 128];
__device__ u32 g_hB[N_NODES * 128];
__device__ u32 g_ag[N_NODES * 128];
__device__ u32 g_W[3 * 128 * 256];      // per layer [c 128][256 words hi/lo interleaved]
__device__ int g_bucket[N_NODES * CAP]; // bucketed adjacency (src lists per dst)
__device__ int g_cursor[N_NODES];       // per-dst fill count == degree
__device__ int g_start[BGRAPH + 1];
__device__ float g_pp[BGRAPH * POOL_CH * 2 * H];

// ---------------- bf16 helpers ----------------------------------------------
__device__ __forceinline__ u32 bf16rn(float f) {
    u32 u = __float_as_uint(f);
    return (u + 0x7fffu + ((u >> 16) & 1u)) >> 16;
}
__device__ __forceinline__ void bfsplit(float f, u32& hi, u32& lo) {
    hi = bf16rn(f);
    float r = f - __uint_as_float(hi << 16);
    lo = bf16rn(r);
}

#define MMA_BF16(c0,c1,c2,c3,a0,a1,a2,a3,b0,b1) \
    asm volatile("mma.sync.aligned.m16n8k16.row.col.f32.bf16.bf16.f32 " \
        "{%0,%1,%2,%3}, {%4,%5,%6,%7}, {%8,%9}, {%0,%1,%2,%3};\n" \
        : "+f"(c0), "+f"(c1), "+f"(c2), "+f"(c3) \
        : "r"(a0), "r"(a1), "r"(a2), "r"(a3), "r"(b0), "r"(b1))

// ---------------- setup: zero cursors + graph start offsets ------------------
__global__ void k_zero_start(const int* __restrict__ batch) {
    int i = blockIdx.x * blockDim.x + threadIdx.x;
    if (i >= N_NODES) return;
    g_cursor[i] = 0;
    int b  = batch[i];
    int bp = (i == 0) ? -1 : batch[i - 1];
    for (int g = bp + 1; g <= b; g++) g_start[g] = i;
    if (i == N_NODES - 1)
        for (int g = b + 1; g <= BGRAPH; g++) g_start[g] = N_NODES;
}

// ---------------- bucket scatter: one pass, no prefix scan -------------------
__global__ void k_scatter(const int* __restrict__ src, const int* __restrict__ dst) {
    int e = blockIdx.x * blockDim.x + threadIdx.x;
    if (e < N_EDGES) {
        int d = dst[e];
        int p = atomicAdd(&g_cursor[d], 1);
        if (p < CAP) g_bucket[d * CAP + p] = src[e];
    }
}

// ---------------- weight split (interleaved): W[c][k] = [Wl ; Wr] ------------
__global__ void k_wsplit(const float* __restrict__ Wl1, const float* __restrict__ Wr1,
                         const float* __restrict__ Wl2, const float* __restrict__ Wr2,
                         const float* __restrict__ Wl3, const float* __restrict__ Wr3) {
    int idx = blockIdx.x * blockDim.x + threadIdx.x;   // pair index
    if (idx >= 3 * 128 * 128) return;
    int l = idx / (128 * 128);
    int r = idx % (128 * 128);
    int c = r >> 7;            // 0..127
    int kp = r & 127;          // k-pair
    int k0 = kp * 2;
    const float* Wl = (l == 0) ? Wl1 : (l == 1) ? Wl2 : Wl3;
    const float* Wr = (l == 0) ? Wr1 : (l == 1) ? Wr2 : Wr3;
    float w0 = (k0 < 128) ? Wl[c * 128 + k0] : Wr[c * 128 + k0 - 128];
    float w1 = (k0 + 1 < 128) ? Wl[c * 128 + k0 + 1] : Wr[c * 128 + k0 + 1 - 128];
    u32 h0, l0, h1, l1;
    bfsplit(w0, h0, l0);
    bfsplit(w1, h1, l1);
    size_t base = (size_t)l * 128 * 256 + (size_t)c * 256 + kp * 2;
    *(uint2*)&g_W[base] = make_uint2(h0 | (h1 << 16), l0 | (l1 << 16));
}

// ---------------- node embedder: relu(LN(x @ W0^T + b0)) -> interleaved ------
__global__ void k_embed(const float* __restrict__ x, const float* __restrict__ W0,
                        const float* __restrict__ b0, const float* __restrict__ g0,
                        const float* __restrict__ be0) {
    int gw = (blockIdx.x * blockDim.x + threadIdx.x) >> 5;
    int lane = threadIdx.x & 31;
    if (gw >= N_NODES) return;
    float xd = (lane < DINP) ? x[gw * DINP + lane] : 0.f;
    float xs[DINP];
#pragma unroll
    for (int d = 0; d < DINP; d++) xs[d] = __shfl_sync(0xffffffffu, xd, d);
    float o[4];
#pragma unroll
    for (int j = 0; j < 4; j++) {
        int c = lane * 4 + j;
        float acc = b0[c];
#pragma unroll
        for (int d = 0; d < DINP; d++) acc = fmaf(xs[d], W0[c * DINP + d], acc);
        o[j] = acc;
    }
    float s1 = o[0] + o[1] + o[2] + o[3];
    float s2 = o[0]*o[0] + o[1]*o[1] + o[2]*o[2] + o[3]*o[3];
#pragma unroll
    for (int off = 16; off; off >>= 1) {
        s1 += __shfl_xor_sync(0xffffffffu, s1, off);
        s2 += __shfl_xor_sync(0xffffffffu, s2, off);
    }
    float m  = s1 * (1.f / H);
    float var = fmaxf(s2 * (1.f / H) - m * m, 0.f);
    float rs = rsqrtf(var + EPS);
    u32 hb[4], lb[4];
#pragma unroll
    for (int j = 0; j < 4; j++) {
        int c = lane * 4 + j;
        float v = fmaxf((o[j] - m) * rs * g0[c] + be0[c], 0.f);
        bfsplit(v, hb[j], lb[j]);
    }
    size_t base = (size_t)gw * 128 + lane * 4;
    *(uint4*)&g_hA[base] = make_uint4(hb[0] | (hb[1] << 16), lb[0] | (lb[1] << 16),
                                      hb[2] | (hb[3] << 16), lb[2] | (lb[3] << 16));
}

// ---------------- mean aggregation: warp per node (bucket adjacency) ---------
__global__ void k_agg(const u32* __restrict__ h) {
    int gw = (blockIdx.x * blockDim.x + threadIdx.x) >> 5;
    int lane = threadIdx.x & 31;
    if (gw >= N_NODES) return;
    int cnt = g_cursor[gw];
    int n = min(cnt, CAP);
    const int* col = &g_bucket[gw * CAP];
    int lane4 = lane * 4;
    float a0 = 0.f, a1 = 0.f, a2 = 0.f, a3 = 0.f;
    float b0 = 0.f, b1 = 0.f, b2 = 0.f, b3 = 0.f;
    int p = 0;
    for (; p + 1 < n; p += 2) {
        int sn0 = __ldg(&col[p]);
        int sn1 = __ldg(&col[p + 1]);
        uint4 w0 = *(const uint4*)&h[(size_t)sn0 * 128 + lane4];
        uint4 w1 = *(const uint4*)&h[(size_t)sn1 * 128 + lane4];
        a0 += __uint_as_float(w0.x << 16) + __uint_as_float(w0.y << 16);
        a1 += __uint_as_float(w0.x & 0xffff0000u) + __uint_as_float(w0.y & 0xffff0000u);
        a2 += __uint_as_float(w0.z << 16) + __uint_as_float(w0.w << 16);
        a3 += __uint_as_float(w0.z & 0xffff0000u) + __uint_as_float(w0.w & 0xffff0000u);
        b0 += __uint_as_float(w1.x << 16) + __uint_as_float(w1.y << 16);
        b1 += __uint_as_float(w1.x & 0xffff0000u) + __uint_as_float(w1.y & 0xffff0000u);
        b2 += __uint_as_float(w1.z << 16) + __uint_as_float(w1.w << 16);
        b3 += __uint_as_float(w1.z & 0xffff0000u) + __uint_as_float(w1.w & 0xffff0000u);
    }
    if (p < n) {
        int sn = __ldg(&col[p]);
        uint4 w = *(const uint4*)&h[(size_t)sn * 128 + lane4];
        a0 += __uint_as_float(w.x << 16) + __uint_as_float(w.y << 16);
        a1 += __uint_as_float(w.x & 0xffff0000u) + __uint_as_float(w.y & 0xffff0000u);
        a2 += __uint_as_float(w.z << 16) + __uint_as_float(w.w << 16);
        a3 += __uint_as_float(w.z & 0xffff0000u) + __uint_as_float(w.w & 0xffff0000u);
    }
    float inv = 1.f / fmaxf((float)cnt, 1.f);
    a0 = (a0 + b0) * inv; a1 = (a1 + b1) * inv;
    a2 = (a2 + b2) * inv; a3 = (a3 + b3) * inv;
    u32 h0, l0, h1, l1, h2, l2, h3, l3;
    bfsplit(a0, h0, l0); bfsplit(a1, h1, l1);
    bfsplit(a2, h2, l2); bfsplit(a3, h3, l3);
    *(uint4*)&g_ag[(size_t)gw * 128 + lane4] =
        make_uint4(h0 | (h1 << 16), l0 | (l1 << 16), h2 | (h3 << 16), l2 | (l3 << 16));
}

// ---------------- tensor-core layer: bf16x3 MMA + LayerNorm + ReLU ----------
// Software-pipelined: chunk c+1 prefetched into registers while chunk c's MMAs
// issue; STS after barrier. Single smem buffer (static < 48 KB).
__global__ void __launch_bounds__(256, 2) k_layer(
    const u32* __restrict__ ag, const u32* __restrict__ h,
    const u32* __restrict__ W,
    const float* __restrict__ bl, const float* __restrict__ gg,
    const float* __restrict__ be,
    float* __restrict__ outF, u32* __restrict__ outI)
{
    __shared__ __align__(16) u32 AsHi[128 * 16];
    __shared__ __align__(16) u32 AsLo[128 * 16];
    __shared__ __align__(16) u32 WsHi[128 * 16];
    __shared__ __align__(16) u32 WsLo[128 * 16];
    __shared__ float sBl[128], sGg[128], sBe[128];

    int t = threadIdx.x;
    int lane = t & 31;
    int wid = t >> 5;
    int g  = lane >> 2;     // 0..7
    int t2 = lane & 3;      // 0..3
    int m0 = wid * 16;
    int nodeBase = blockIdx.x * 128;

    if (t < 128) { sBl[t] = bl[t]; sGg[t] = gg[t]; sBe[t] = be[t]; }

    // precompute per-it staging indices (invariant across chunks)
    int sRow[8], sJ32[8], sIdx[8];
#pragma unroll
    for (int it = 0; it < 8; it++) {
        int i = it * 256 + t;
        int row = i >> 4;
        int j32 = i & 15;
        int blk = j32 >> 3, j = j32 & 7;
        int pj = (j < 4) ? (2 * j) : (2 * j - 7);
        sRow[it] = row;
        sJ32[it] = j32;
        sIdx[it] = (row * 16 + blk * 8 + pj) ^ (((row >> 1) & 1) << 3);
    }

    float acc[16][4];
#pragma unroll
    for (int nt = 0; nt < 16; nt++)
#pragma unroll
        for (int j = 0; j < 4; j++) acc[nt][j] = 0.f;

    // ---- prologue: stage chunk 0 (from ag) directly ----
#pragma unroll
    for (int it = 0; it < 8; it++) {
        int gnode = nodeBase + sRow[it];
        uint2 v = make_uint2(0u, 0u);
        if (gnode < N_NODES)
            v = *(const uint2*)&ag[(size_t)gnode * 128 + 2 * sJ32[it]];
        AsHi[sIdx[it]] = v.x; AsLo[sIdx[it]] = v.y;
        uint2 w = *(const uint2*)&W[(size_t)sRow[it] * 256 + 2 * sJ32[it]];
        WsHi[sIdx[it]] = w.x; WsLo[sIdx[it]] = w.y;
    }
    __syncthreads();

#pragma unroll 1
    for (int kk = 0; kk < 256; kk += 32) {
        // ---- prefetch chunk kk+32 into registers ----
        uint2 va[8], vw[8];
        bool have = (kk + 32) < 256;
        if (have) {
            int kn = kk + 32;
            const u32* feat = (kn < 128) ? ag : h;
            int koff = (kn < 128) ? kn : kn - 128;
#pragma unroll
            for (int it = 0; it < 8; it++) {
                int gnode = nodeBase + sRow[it];
                va[it] = make_uint2(0u, 0u);
                if (gnode < N_NODES)
                    va[it] = *(const uint2*)&feat[(size_t)gnode * 128 + koff + 2 * sJ32[it]];
                vw[it] = *(const uint2*)&W[(size_t)sRow[it] * 256 + kn + 2 * sJ32[it]];
            }
        }

        // ---- compute on current buffer ----
#pragma unroll
        for (int blk = 0; blk < 2; blk++) {
            int rA = m0 + g, rB = m0 + g + 8;
            int iA = (rA * 16 + blk * 8 + 2 * t2) ^ (((rA >> 1) & 1) << 3);
            int iB = (rB * 16 + blk * 8 + 2 * t2) ^ (((rB >> 1) & 1) << 3);
            uint2 a02h = *(const uint2*)&AsHi[iA];
            uint2 a13h = *(const uint2*)&AsHi[iB];
            uint2 a02l = *(const uint2*)&AsLo[iA];
            uint2 a13l = *(const uint2*)&AsLo[iB];
#pragma unroll
            for (int nt = 0; nt < 16; nt++) {
                int c = nt * 8 + g;
                int iW = (c * 16 + blk * 8 + 2 * t2) ^ (((c >> 1) & 1) << 3);
                uint2 bh = *(const uint2*)&WsHi[iW];
                uint2 blo = *(const uint2*)&WsLo[iW];
                MMA_BF16(acc[nt][0], acc[nt][1], acc[nt][2], acc[nt][3],
                         a02h.x, a13h.x, a02h.y, a13h.y, bh.x, bh.y);
                MMA_BF16(acc[nt][0], acc[nt][1], acc[nt][2], acc[nt][3],
                         a02h.x, a13h.x, a02h.y, a13h.y, blo.x, blo.y);
                MMA_BF16(acc[nt][0], acc[nt][1], acc[nt][2], acc[nt][3],
                         a02l.x, a13l.x, a02l.y, a13l.y, bh.x, bh.y);
            }
        }
        __syncthreads();
        if (have) {
#pragma unroll
            for (int it = 0; it < 8; it++) {
                AsHi[sIdx[it]] = va[it].x; AsLo[sIdx[it]] = va[it].y;
                WsHi[sIdx[it]] = vw[it].x; WsLo[sIdx[it]] = vw[it].y;
            }
            __syncthreads();
        }
    }

    // ---- epilogue ----
    float sA1 = 0.f, sA2 = 0.f, sB1 = 0.f, sB2 = 0.f;
#pragma unroll
    for (int nt = 0; nt < 16; nt++) {
        int c0 = nt * 8 + 2 * t2;
        float b0 = sBl[c0], b1 = sBl[c0 + 1];
        float va0 = acc[nt][0] + b0, va1 = acc[nt][1] + b1;
        float vb0 = acc[nt][2] + b0, vb1 = acc[nt][3] + b1;
        sA1 += va0 + va1; sA2 += va0 * va0 + va1 * va1;
        sB1 += vb0 + vb1; sB2 += vb0 * vb0 + vb1 * vb1;
    }
#pragma unroll
    for (int off = 1; off <= 2; off <<= 1) {
        sA1 += __shfl_xor_sync(0xffffffffu, sA1, off);
        sA2 += __shfl_xor_sync(0xffffffffu, sA2, off);
        sB1 += __shfl_xor_sync(0xffffffffu, sB1, off);
        sB2 += __shfl_xor_sync(0xffffffffu, sB2, off);
    }
    float mA = sA1 * (1.f / H);
    float vA = fmaxf(sA2 * (1.f / H) - mA * mA, 0.f);
    float rsA = rsqrtf(vA + EPS);
    float mB = sB1 * (1.f / H);
    float vB = fmaxf(sB2 * (1.f / H) - mB * mB, 0.f);
    float rsB = rsqrtf(vB + EPS);

    int gA = nodeBase + m0 + g;
    int gB = gA + 8;
    bool wA = gA < N_NODES, wB = gB < N_NODES;

#pragma unroll
    for (int nt = 0; nt < 16; nt++) {
        int c0 = nt * 8 + 2 * t2;
        float b0 = sBl[c0], b1 = sBl[c0 + 1];
        float gg0 = sGg[c0], gg1 = sGg[c0 + 1];
        float be0 = sBe[c0], be1 = sBe[c0 + 1];
        float oa0 = fmaxf((acc[nt][0] + b0 - mA) * rsA * gg0 + be0, 0.f);
        float oa1 = fmaxf((acc[nt][1] + b1 - mA) * rsA * gg1 + be1, 0.f);
        float ob0 = fmaxf((acc[nt][2] + b0 - mB) * rsB * gg0 + be0, 0.f);
        float ob1 = fmaxf((acc[nt][3] + b1 - mB) * rsB * gg1 + be1, 0.f);
        if (outF) {
            if (wA) *(float2*)&outF[(size_t)gA * 128 + c0] = make_float2(oa0, oa1);
            if (wB) *(float2*)&outF[(size_t)gB * 128 + c0] = make_float2(ob0, ob1);
        } else {
            u32 h0, l0, h1, l1;
            if (wA) {
                bfsplit(oa0, h0, l0); bfsplit(oa1, h1, l1);
                *(uint2*)&outI[(size_t)gA * 128 + c0] =
                    make_uint2(h0 | (h1 << 16), l0 | (l1 << 16));
            }
            if (wB) {
                bfsplit(ob0, h0, l0); bfsplit(ob1, h1, l1);
                *(uint2*)&outI[(size_t)gB * 128 + c0] =
                    make_uint2(h0 | (h1 << 16), l0 | (l1 << 16));
            }
        }
    }
}

// ---------------- pooling (two-stage) ---------------------------------------
__global__ void k_poolA(const float* __restrict__ ne) {
    int b  = blockIdx.x / POOL_CH;
    int ch = blockIdx.x % POOL_CH;
    int c  = threadIdx.x;
    int s = g_start[b], e = g_start[b + 1];
    int len = e - s;
    int cs = s + (int)(((long long)len * ch) / POOL_CH);
    int ce = s + (int)(((long long)len * (ch + 1)) / POOL_CH);
    float sum = 0.f, mx = -FLT_MAX;
    for (int n = cs; n < ce; n++) {
        float v = ne[(size_t)n * H + c];
        sum += v;
        mx = fmaxf(mx, v);
    }
    size_t base = ((size_t)(b * POOL_CH + ch)) * 2 * H;
    g_pp[base + c]     = sum;
    g_pp[base + H + c] = mx;
}

__global__ void k_poolB(float* __restrict__ out) {
    int b = blockIdx.x;
    int c = threadIdx.x;
    int s = g_start[b], e = g_start[b + 1];
    float sum = 0.f, mx = -FLT_MAX;
#pragma unroll
    for (int ch = 0; ch < POOL_CH; ch++) {
        size_t base = ((size_t)(b * POOL_CH + ch)) * 2 * H;
        sum += g_pp[base + c];
        mx = fmaxf(mx, g_pp[base + H + c]);
    }
    float cnt = (float)(e - s);
    size_t gbase = (size_t)N_NODES * H + (size_t)b * 2 * H;
    out[gbase + c]     = sum / fmaxf(cnt, 1.f);
    out[gbase + H + c] = mx;
}

// ---------------- launch ----------------------------------------------------
extern "C" void kernel_launch(void* const* d_in, const int* in_sizes, int n_in,
                              void* d_out, int out_size) {
    const float* x     = (const float*)d_in[0];
    const int*   ei    = (const int*)  d_in[1];
    const int*   batch = (const int*)  d_in[2];
    const float* W0  = (const float*)d_in[3];
    const float* b0  = (const float*)d_in[4];
    const float* g0  = (const float*)d_in[5];
    const float* be0 = (const float*)d_in[6];
    const float* Wl1 = (const float*)d_in[7];
    const float* bl1 = (const float*)d_in[8];
    const float* Wr1 = (const float*)d_in[9];
    const float* g1  = (const float*)d_in[10];
    const float* be1 = (const float*)d_in[11];
    const float* Wl2 = (const float*)d_in[12];
    const float* bl2 = (const float*)d_in[13];
    const float* Wr2 = (const float*)d_in[14];
    const float* g2  = (const float*)d_in[15];
    const float* be2 = (const float*)d_in[16];
    const float* Wl3 = (const float*)d_in[17];
    const float* bl3 = (const float*)d_in[18];
    const float* Wr3 = (const float*)d_in[19];
    const float* g3  = (const float*)d_in[20];
    const float* be3 = (const float*)d_in[21];

    const int* src = ei;
    const int* dst = ei + N_EDGES;
    float* out = (float*)d_out;

    u32 *hA, *hB, *ag, *W;
    cudaGetSymbolAddress((void**)&hA, g_hA);
    cudaGetSymbolAddress((void**)&hB, g_hB);
    cudaGetSymbolAddress((void**)&ag, g_ag);
    cudaGetSymbolAddress((void**)&W, g_W);

    const int nodeBlocks = (N_NODES + 255) / 256;
    const int edgeBlocks = (N_EDGES + 255) / 256;
    const int warpBlocks = (N_NODES + 7) / 8;          // 8 warps/block
    const int tileBlocks = (N_NODES + 127) / 128;      // 782

    // adjacency build: zero+start, then single-pass bucket scatter
    k_zero_start<<<nodeBlocks, 256>>>(batch);
    k_scatter<<<edgeBlocks, 256>>>(src, dst);

    k_wsplit<<<(3 * 128 * 128 + 255) / 256, 256>>>(Wl1, Wr1, Wl2, Wr2, Wl3, Wr3);
    k_embed<<<warpBlocks, 256>>>(x, W0, b0, g0, be0);

    // layer 1: A -> B
    k_agg<<<warpBlocks, 256>>>(hA);
    k_layer<<<tileBlocks, 256>>>(ag, hA, W + 0 * 128 * 256, bl1, g1, be1, nullptr, hB);
    // layer 2: B -> A
    k_agg<<<warpBlocks, 256>>>(hB);
    k_layer<<<tileBlocks, 256>>>(ag, hB, W + 1 * 128 * 256, bl2, g2, be2, nullptr, hA);
    // layer 3: A -> out (fp32 node_embed)
    k_agg<<<warpBlocks, 256>>>(hA);
    k_layer<<<tileBlocks, 256>>>(ag, hA, W + 2 * 128 * 256, bl3, g3, be3, out, nullptr);

    k_poolA<<<BGRAPH * POOL_CH, H>>>(out);
    k_poolB<<<BGRAPH, H>>>(out);
}

// round 15
// speedup vs baseline: 1.1708x; 1.1708x over previous
#include <cuda_runtime.h>
#include <cfloat>
#include <stdint.h>

#define N_NODES 100000
#define N_EDGES 1600000
#define BGRAPH  64
#define DINP    9
#define H       128
#define EPS     1e-5f

#define SCAN_BLK 512
#define SCAN_NB  196   // ceil(100000/512)
#define POOL_CH  16
#define EMB_BLOCKS 782 // 6256 warps -> ~16 nodes/warp (weights amortized)

typedef unsigned u32;

// ---------------- scratch (device globals; no allocation allowed) -----------
// Interleaved bf16 hi/lo storage per node: 128 u32 words.
// word[2p] = hi pair p (ch 2p lo16, 2p+1 hi16); word[2p+1] = lo pair p.
__device__ u32 g_hA[N_NODES * 128];
__device__ u32 g_hB[N_NODES * 128];
__device__ u32 g_ag[N_NODES * 128];
__device__ u32 g_W[3 * 128 * 256];      // per layer [c 128][256 words hi/lo interleaved]
__device__ int g_rowptr[N_NODES + 1];
__device__ int g_col[N_EDGES];
__device__ int g_deg[N_NODES];
__device__ int g_cursor[N_NODES];
__device__ int g_bsum[SCAN_NB];
__device__ int g_start[BGRAPH + 1];
__device__ float g_pp[BGRAPH * POOL_CH * 2 * H];

// ---------------- bf16 helpers ----------------------------------------------
__device__ __forceinline__ u32 bf16rn(float f) {
    u32 u = __float_as_uint(f);
    return (u + 0x7fffu + ((u >> 16) & 1u)) >> 16;
}
__device__ __forceinline__ void bfsplit(float f, u32& hi, u32& lo) {
    hi = bf16rn(f);
    float r = f - __uint_as_float(hi << 16);
    lo = bf16rn(r);
}

#define MMA_BF16(c0,c1,c2,c3,a0,a1,a2,a3,b0,b1) \
    asm volatile("mma.sync.aligned.m16n8k16.row.col.f32.bf16.bf16.f32 " \
        "{%0,%1,%2,%3}, {%4,%5,%6,%7}, {%8,%9}, {%0,%1,%2,%3};\n" \
        : "+f"(c0), "+f"(c1), "+f"(c2), "+f"(c3) \
        : "r"(a0), "r"(a1), "r"(a2), "r"(a3), "r"(b0), "r"(b1))

// ---------------- CSR build -------------------------------------------------
__global__ void k_zero() {
    int i = blockIdx.x * blockDim.x + threadIdx.x;
    if (i < N_NODES) { g_deg[i] = 0; g_cursor[i] = 0; }
}

__global__ void k_deg(const int* __restrict__ dst) {
    int e = blockIdx.x * blockDim.x + threadIdx.x;
    if (e < N_EDGES) atomicAdd(&g_deg[dst[e]], 1);
}

__global__ void k_scan1() {
    __shared__ int sh[SCAN_BLK];
    int t = threadIdx.x;
    int i = blockIdx.x * SCAN_BLK + t;
    int v = (i < N_NODES) ? g_deg[i] : 0;
    sh[t] = v; __syncthreads();
    for (int o = 1; o < SCAN_BLK; o <<= 1) {
        int a = (t >= o) ? sh[t - o] : 0;
        __syncthreads();
        sh[t] += a;
        __syncthreads();
    }
    if (i < N_NODES) g_rowptr[i] = sh[t] - v;
    if (t == SCAN_BLK - 1) g_bsum[blockIdx.x] = sh[t];
}

__global__ void k_scan2() {
    __shared__ int sh[256];
    int t = threadIdx.x;
    int v = (t < SCAN_NB) ? g_bsum[t] : 0;
    sh[t] = v; __syncthreads();
    for (int o = 1; o < 256; o <<= 1) {
        int a = (t >= o) ? sh[t - o] : 0;
        __syncthreads();
        sh[t] += a;
        __syncthreads();
    }
    if (t < SCAN_NB) g_bsum[t] = sh[t] - v;
    if (t == 0) g_rowptr[N_NODES] = N_EDGES;
}

__global__ void k_scan3() {
    int i = blockIdx.x * SCAN_BLK + threadIdx.x;
    if (i < N_NODES) g_rowptr[i] += g_bsum[blockIdx.x];
}

__global__ void k_scatter(const int* __restrict__ src, const int* __restrict__ dst) {
    int e = blockIdx.x * blockDim.x + threadIdx.x;
    if (e < N_EDGES) {
        int d = dst[e];
        int p = atomicAdd(&g_cursor[d], 1);
        g_col[g_rowptr[d] + p] = src[e];
    }
}

// ---------------- weight split (interleaved): W[c][k] = [Wl ; Wr] ------------
__global__ void k_wsplit(const float* __restrict__ Wl1, const float* __restrict__ Wr1,
                         const float* __restrict__ Wl2, const float* __restrict__ Wr2,
                         const float* __restrict__ Wl3, const float* __restrict__ Wr3) {
    int idx = blockIdx.x * blockDim.x + threadIdx.x;   // pair index
    if (idx >= 3 * 128 * 128) return;
    int l = idx / (128 * 128);
    int r = idx % (128 * 128);
    int c = r >> 7;            // 0..127
    int kp = r & 127;          // k-pair
    int k0 = kp * 2;
    const float* Wl = (l == 0) ? Wl1 : (l == 1) ? Wl2 : Wl3;
    const float* Wr = (l == 0) ? Wr1 : (l == 1) ? Wr2 : Wr3;
    float w0 = (k0 < 128) ? Wl[c * 128 + k0] : Wr[c * 128 + k0 - 128];
    float w1 = (k0 + 1 < 128) ? Wl[c * 128 + k0 + 1] : Wr[c * 128 + k0 + 1 - 128];
    u32 h0, l0, h1, l1;
    bfsplit(w0, h0, l0);
    bfsplit(w1, h1, l1);
    size_t base = (size_t)l * 128 * 256 + (size_t)c * 256 + kp * 2;
    *(uint2*)&g_W[base] = make_uint2(h0 | (h1 << 16), l0 | (l1 << 16));
}

// ---------------- node embedder: register-resident W0, grid-stride ----------
// Each lane owns 4 channels (c = lane*4+j): loads W0 rows + params ONCE into
// registers, then loops over nodes. Per node: 1 x-load + 9 shfl + 36 FFMA + LN.
__global__ void __launch_bounds__(256) k_embed(
    const float* __restrict__ x, const float* __restrict__ W0,
    const float* __restrict__ b0, const float* __restrict__ g0,
    const float* __restrict__ be0)
{
    int warpId = (blockIdx.x * blockDim.x + threadIdx.x) >> 5;
    int lane = threadIdx.x & 31;
    int nwarps = EMB_BLOCKS * 8;

    // register-resident weights/params for this lane's 4 channels
    float w[4][DINP];
    float bb[4], gm[4], bt[4];
#pragma unroll
    for (int j = 0; j < 4; j++) {
        int c = lane * 4 + j;
#pragma unroll
        for (int d = 0; d < DINP; d++) w[j][d] = W0[c * DINP + d];
        bb[j] = b0[c]; gm[j] = g0[c]; bt[j] = be0[c];
    }

    for (int gw = warpId; gw < N_NODES; gw += nwarps) {
        float xd = (lane < DINP) ? __ldg(&x[gw * DINP + lane]) : 0.f;
        float xs[DINP];
#pragma unroll
        for (int d = 0; d < DINP; d++) xs[d] = __shfl_sync(0xffffffffu, xd, d);
        float o[4];
#pragma unroll
        for (int j = 0; j < 4; j++) {
            float acc = bb[j];
#pragma unroll
            for (int d = 0; d < DINP; d++) acc = fmaf(xs[d], w[j][d], acc);
            o[j] = acc;
        }
        float s1 = o[0] + o[1] + o[2] + o[3];
        float s2 = o[0]*o[0] + o[1]*o[1] + o[2]*o[2] + o[3]*o[3];
#pragma unroll
        for (int off = 16; off; off >>= 1) {
            s1 += __shfl_xor_sync(0xffffffffu, s1, off);
            s2 += __shfl_xor_sync(0xffffffffu, s2, off);
        }
        float m  = s1 * (1.f / H);
        float var = fmaxf(s2 * (1.f / H) - m * m, 0.f);
        float rs = rsqrtf(var + EPS);
        u32 hb[4], lb[4];
#pragma unroll
        for (int j = 0; j < 4; j++) {
            float v = fmaxf((o[j] - m) * rs * gm[j] + bt[j], 0.f);
            bfsplit(v, hb[j], lb[j]);
        }
        *(uint4*)&g_hA[(size_t)gw * 128 + lane * 4] =
            make_uint4(hb[0] | (hb[1] << 16), lb[0] | (lb[1] << 16),
                       hb[2] | (hb[3] << 16), lb[2] | (lb[3] << 16));
    }
}

// ---------------- mean aggregation: warp per node ----------------------------
__global__ void k_agg(const u32* __restrict__ h) {
    int gw = (blockIdx.x * blockDim.x + threadIdx.x) >> 5;
    int lane = threadIdx.x & 31;
    if (gw >= N_NODES) return;
    int s = g_rowptr[gw], e = g_rowptr[gw + 1];
    int lane4 = lane * 4;
    float a0 = 0.f, a1 = 0.f, a2 = 0.f, a3 = 0.f;
    float b0 = 0.f, b1 = 0.f, b2 = 0.f, b3 = 0.f;
    int p = s;
    for (; p + 1 < e; p += 2) {
        int sn0 = __ldg(&g_col[p]);
        int sn1 = __ldg(&g_col[p + 1]);
        uint4 w0 = *(const uint4*)&h[(size_t)sn0 * 128 + lane4];
        uint4 w1 = *(const uint4*)&h[(size_t)sn1 * 128 + lane4];
        a0 += __uint_as_float(w0.x << 16) + __uint_as_float(w0.y << 16);
        a1 += __uint_as_float(w0.x & 0xffff0000u) + __uint_as_float(w0.y & 0xffff0000u);
        a2 += __uint_as_float(w0.z << 16) + __uint_as_float(w0.w << 16);
        a3 += __uint_as_float(w0.z & 0xffff0000u) + __uint_as_float(w0.w & 0xffff0000u);
        b0 += __uint_as_float(w1.x << 16) + __uint_as_float(w1.y << 16);
        b1 += __uint_as_float(w1.x & 0xffff0000u) + __uint_as_float(w1.y & 0xffff0000u);
        b2 += __uint_as_float(w1.z << 16) + __uint_as_float(w1.w << 16);
        b3 += __uint_as_float(w1.z & 0xffff0000u) + __uint_as_float(w1.w & 0xffff0000u);
    }
    if (p < e) {
        int sn = __ldg(&g_col[p]);
        uint4 w = *(const uint4*)&h[(size_t)sn * 128 + lane4];
        a0 += __uint_as_float(w.x << 16) + __uint_as_float(w.y << 16);
        a1 += __uint_as_float(w.x & 0xffff0000u) + __uint_as_float(w.y & 0xffff0000u);
        a2 += __uint_as_float(w.z << 16) + __uint_as_float(w.w << 16);
        a3 += __uint_as_float(w.z & 0xffff0000u) + __uint_as_float(w.w & 0xffff0000u);
    }
    float inv = 1.f / fmaxf((float)(e - s), 1.f);
    a0 = (a0 + b0) * inv; a1 = (a1 + b1) * inv;
    a2 = (a2 + b2) * inv; a3 = (a3 + b3) * inv;
    u32 h0, l0, h1, l1, h2, l2, h3, l3;
    bfsplit(a0, h0, l0); bfsplit(a1, h1, l1);
    bfsplit(a2, h2, l2); bfsplit(a3, h3, l3);
    *(uint4*)&g_ag[(size_t)gw * 128 + lane4] =
        make_uint4(h0 | (h1 << 16), l0 | (l1 << 16), h2 | (h3 << 16), l2 | (l3 << 16));
}

// ---------------- tensor-core layer: bf16x3 MMA + LayerNorm + ReLU ----------
// Software-pipelined: chunk c+1 prefetched into registers while chunk c's MMAs
// issue; STS after barrier. Single smem buffer (static < 48 KB).
__global__ void __launch_bounds__(256, 2) k_layer(
    const u32* __restrict__ ag, const u32* __restrict__ h,
    const u32* __restrict__ W,
    const float* __restrict__ bl, const float* __restrict__ gg,
    const float* __restrict__ be,
    float* __restrict__ outF, u32* __restrict__ outI)
{
    __shared__ __align__(16) u32 AsHi[128 * 16];
    __shared__ __align__(16) u32 AsLo[128 * 16];
    __shared__ __align__(16) u32 WsHi[128 * 16];
    __shared__ __align__(16) u32 WsLo[128 * 16];
    __shared__ float sBl[128], sGg[128], sBe[128];

    int t = threadIdx.x;
    int lane = t & 31;
    int wid = t >> 5;
    int g  = lane >> 2;     // 0..7
    int t2 = lane & 3;      // 0..3
    int m0 = wid * 16;
    int nodeBase = blockIdx.x * 128;

    if (t < 128) { sBl[t] = bl[t]; sGg[t] = gg[t]; sBe[t] = be[t]; }

    int sRow[8], sJ32[8], sIdx[8];
#pragma unroll
    for (int it = 0; it < 8; it++) {
        int i = it * 256 + t;
        int row = i >> 4;
        int j32 = i & 15;
        int blk = j32 >> 3, j = j32 & 7;
        int pj = (j < 4) ? (2 * j) : (2 * j - 7);
        sRow[it] = row;
        sJ32[it] = j32;
        sIdx[it] = (row * 16 + blk * 8 + pj) ^ (((row >> 1) & 1) << 3);
    }

    float acc[16][4];
#pragma unroll
    for (int nt = 0; nt < 16; nt++)
#pragma unroll
        for (int j = 0; j < 4; j++) acc[nt][j] = 0.f;

#pragma unroll
    for (int it = 0; it < 8; it++) {
        int gnode = nodeBase + sRow[it];
        uint2 v = make_uint2(0u, 0u);
        if (gnode < N_NODES)
            v = *(const uint2*)&ag[(size_t)gnode * 128 + 2 * sJ32[it]];
        AsHi[sIdx[it]] = v.x; AsLo[sIdx[it]] = v.y;
        uint2 w = *(const uint2*)&W[(size_t)sRow[it] * 256 + 2 * sJ32[it]];
        WsHi[sIdx[it]] = w.x; WsLo[sIdx[it]] = w.y;
    }
    __syncthreads();

#pragma unroll 1
    for (int kk = 0; kk < 256; kk += 32) {
        uint2 va[8], vw[8];
        bool have = (kk + 32) < 256;
        if (have) {
            int kn = kk + 32;
            const u32* feat = (kn < 128) ? ag : h;
            int koff = (kn < 128) ? kn : kn - 128;
#pragma unroll
            for (int it = 0; it < 8; it++) {
                int gnode = nodeBase + sRow[it];
                va[it] = make_uint2(0u, 0u);
                if (gnode < N_NODES)
                    va[it] = *(const uint2*)&feat[(size_t)gnode * 128 + koff + 2 * sJ32[it]];
                vw[it] = *(const uint2*)&W[(size_t)sRow[it] * 256 + kn + 2 * sJ32[it]];
            }
        }

#pragma unroll
        for (int blk = 0; blk < 2; blk++) {
            int rA = m0 + g, rB = m0 + g + 8;
            int iA = (rA * 16 + blk * 8 + 2 * t2) ^ (((rA >> 1) & 1) << 3);
            int iB = (rB * 16 + blk * 8 + 2 * t2) ^ (((rB >> 1) & 1) << 3);
            uint2 a02h = *(const uint2*)&AsHi[iA];
            uint2 a13h = *(const uint2*)&AsHi[iB];
            uint2 a02l = *(const uint2*)&AsLo[iA];
            uint2 a13l = *(const uint2*)&AsLo[iB];
#pragma unroll
            for (int nt = 0; nt < 16; nt++) {
                int c = nt * 8 + g;
                int iW = (c * 16 + blk * 8 + 2 * t2) ^ (((c >> 1) & 1) << 3);
                uint2 bh = *(const uint2*)&WsHi[iW];
                uint2 blo = *(const uint2*)&WsLo[iW];
                MMA_BF16(acc[nt][0], acc[nt][1], acc[nt][2], acc[nt][3],
                         a02h.x, a13h.x, a02h.y, a13h.y, bh.x, bh.y);
                MMA_BF16(acc[nt][0], acc[nt][1], acc[nt][2], acc[nt][3],
                         a02h.x, a13h.x, a02h.y, a13h.y, blo.x, blo.y);
                MMA_BF16(acc[nt][0], acc[nt][1], acc[nt][2], acc[nt][3],
                         a02l.x, a13l.x, a02l.y, a13l.y, bh.x, bh.y);
            }
        }
        __syncthreads();
        if (have) {
#pragma unroll
            for (int it = 0; it < 8; it++) {
                AsHi[sIdx[it]] = va[it].x; AsLo[sIdx[it]] = va[it].y;
                WsHi[sIdx[it]] = vw[it].x; WsLo[sIdx[it]] = vw[it].y;
            }
            __syncthreads();
        }
    }

    // ---- epilogue ----
    float sA1 = 0.f, sA2 = 0.f, sB1 = 0.f, sB2 = 0.f;
#pragma unroll
    for (int nt = 0; nt < 16; nt++) {
        int c0 = nt * 8 + 2 * t2;
        float b0 = sBl[c0], b1 = sBl[c0 + 1];
        float va0 = acc[nt][0] + b0, va1 = acc[nt][1] + b1;
        float vb0 = acc[nt][2] + b0, vb1 = acc[nt][3] + b1;
        sA1 += va0 + va1; sA2 += va0 * va0 + va1 * va1;
        sB1 += vb0 + vb1; sB2 += vb0 * vb0 + vb1 * vb1;
    }
#pragma unroll
    for (int off = 1; off <= 2; off <<= 1) {
        sA1 += __shfl_xor_sync(0xffffffffu, sA1, off);
        sA2 += __shfl_xor_sync(0xffffffffu, sA2, off);
        sB1 += __shfl_xor_sync(0xffffffffu, sB1, off);
        sB2 += __shfl_xor_sync(0xffffffffu, sB2, off);
    }
    float mA = sA1 * (1.f / H);
    float vA = fmaxf(sA2 * (1.f / H) - mA * mA, 0.f);
    float rsA = rsqrtf(vA + EPS);
    float mB = sB1 * (1.f / H);
    float vB = fmaxf(sB2 * (1.f / H) - mB * mB, 0.f);
    float rsB = rsqrtf(vB + EPS);

    int gA = nodeBase + m0 + g;
    int gB = gA + 8;
    bool wA = gA < N_NODES, wB = gB < N_NODES;

#pragma unroll
    for (int nt = 0; nt < 16; nt++) {
        int c0 = nt * 8 + 2 * t2;
        float b0 = sBl[c0], b1 = sBl[c0 + 1];
        float gg0 = sGg[c0], gg1 = sGg[c0 + 1];
        float be0 = sBe[c0], be1 = sBe[c0 + 1];
        float oa0 = fmaxf((acc[nt][0] + b0 - mA) * rsA * gg0 + be0, 0.f);
        float oa1 = fmaxf((acc[nt][1] + b1 - mA) * rsA * gg1 + be1, 0.f);
        float ob0 = fmaxf((acc[nt][2] + b0 - mB) * rsB * gg0 + be0, 0.f);
        float ob1 = fmaxf((acc[nt][3] + b1 - mB) * rsB * gg1 + be1, 0.f);
        if (outF) {
            if (wA) *(float2*)&outF[(size_t)gA * 128 + c0] = make_float2(oa0, oa1);
            if (wB) *(float2*)&outF[(size_t)gB * 128 + c0] = make_float2(ob0, ob1);
        } else {
            u32 h0, l0, h1, l1;
            if (wA) {
                bfsplit(oa0, h0, l0); bfsplit(oa1, h1, l1);
                *(uint2*)&outI[(size_t)gA * 128 + c0] =
                    make_uint2(h0 | (h1 << 16), l0 | (l1 << 16));
            }
            if (wB) {
                bfsplit(ob0, h0, l0); bfsplit(ob1, h1, l1);
                *(uint2*)&outI[(size_t)gB * 128 + c0] =
                    make_uint2(h0 | (h1 << 16), l0 | (l1 << 16));
            }
        }
    }
}

// ---------------- pooling (two-stage) ---------------------------------------
__global__ void k_startk(const int* __restrict__ batch) {
    int i = blockIdx.x * blockDim.x + threadIdx.x;
    if (i >= N_NODES) return;
    int b  = batch[i];
    int bp = (i == 0) ? -1 : batch[i - 1];
    for (int g = bp + 1; g <= b; g++) g_start[g] = i;
    if (i == N_NODES - 1)
        for (int g = b + 1; g <= BGRAPH; g++) g_start[g] = N_NODES;
}

__global__ void k_poolA(const float* __restrict__ ne) {
    int b  = blockIdx.x / POOL_CH;
    int ch = blockIdx.x % POOL_CH;
    int c  = threadIdx.x;
    int s = g_start[b], e = g_start[b + 1];
    int len = e - s;
    int cs = s + (int)(((long long)len * ch) / POOL_CH);
    int ce = s + (int)(((long long)len * (ch + 1)) / POOL_CH);
    float sum = 0.f, mx = -FLT_MAX;
    for (int n = cs; n < ce; n++) {
        float v = ne[(size_t)n * H + c];
        sum += v;
        mx = fmaxf(mx, v);
    }
    size_t base = ((size_t)(b * POOL_CH + ch)) * 2 * H;
    g_pp[base + c]     = sum;
    g_pp[base + H + c] = mx;
}

__global__ void k_poolB(float* __restrict__ out) {
    int b = blockIdx.x;
    int c = threadIdx.x;
    int s = g_start[b], e = g_start[b + 1];
    float sum = 0.f, mx = -FLT_MAX;
#pragma unroll
    for (int ch = 0; ch < POOL_CH; ch++) {
        size_t base = ((size_t)(b * POOL_CH + ch)) * 2 * H;
        sum += g_pp[base + c];
        mx = fmaxf(mx, g_pp[base + H + c]);
    }
    float cnt = (float)(e - s);
    size_t gbase = (size_t)N_NODES * H + (size_t)b * 2 * H;
    out[gbase + c]     = sum / fmaxf(cnt, 1.f);
    out[gbase + H + c] = mx;
}

// ---------------- launch ----------------------------------------------------
extern "C" void kernel_launch(void* const* d_in, const int* in_sizes, int n_in,
                              void* d_out, int out_size) {
    const float* x     = (const float*)d_in[0];
    const int*   ei    = (const int*)  d_in[1];
    const int*   batch = (const int*)  d_in[2];
    const float* W0  = (const float*)d_in[3];
    const float* b0  = (const float*)d_in[4];
    const float* g0  = (const float*)d_in[5];
    const float* be0 = (const float*)d_in[6];
    const float* Wl1 = (const float*)d_in[7];
    const float* bl1 = (const float*)d_in[8];
    const float* Wr1 = (const float*)d_in[9];
    const float* g1  = (const float*)d_in[10];
    const float* be1 = (const float*)d_in[11];
    const float* Wl2 = (const float*)d_in[12];
    const float* bl2 = (const float*)d_in[13];
    const float* Wr2 = (const float*)d_in[14];
    const float* g2  = (const float*)d_in[15];
    const float* be2 = (const float*)d_in[16];
    const float* Wl3 = (const float*)d_in[17];
    const float* bl3 = (const float*)d_in[18];
    const float* Wr3 = (const float*)d_in[19];
    const float* g3  = (const float*)d_in[20];
    const float* be3 = (const float*)d_in[21];

    const int* src = ei;
    const int* dst = ei + N_EDGES;
    float* out = (float*)d_out;

    u32 *hA, *hB, *ag, *W;
    cudaGetSymbolAddress((void**)&hA, g_hA);
    cudaGetSymbolAddress((void**)&hB, g_hB);
    cudaGetSymbolAddress((void**)&ag, g_ag);
    cudaGetSymbolAddress((void**)&W, g_W);

    const int nodeBlocks = (N_NODES + 255) / 256;
    const int edgeBlocks = (N_EDGES + 255) / 256;
    const int warpBlocks = (N_NODES + 7) / 8;          // 8 warps/block
    const int tileBlocks = (N_NODES + 127) / 128;      // 782

    // CSR build (every launch — caching is forbidden)
    k_zero<<<nodeBlocks, 256>>>();
    k_deg<<<edgeBlocks, 256>>>(dst);
    k_scan1<<<SCAN_NB, SCAN_BLK>>>();
    k_scan2<<<1, 256>>>();
    k_scan3<<<SCAN_NB, SCAN_BLK>>>();
    k_scatter<<<edgeBlocks, 256>>>(src, dst);

    k_wsplit<<<(3 * 128 * 128 + 255) / 256, 256>>>(Wl1, Wr1, Wl2, Wr2, Wl3, Wr3);

    k_embed<<<EMB_BLOCKS, 256>>>(x, W0, b0, g0, be0);
    k_startk<<<nodeBlocks, 256>>>(batch);

    // layer 1: A -> B
    k_agg<<<warpBlocks, 256>>>(hA);
    k_layer<<<tileBlocks, 256>>>(ag, hA, W + 0 * 128 * 256, bl1, g1, be1, nullptr, hB);
    // layer 2: B -> A
    k_agg<<<warpBlocks, 256>>>(hB);
    k_layer<<<tileBlocks, 256>>>(ag, hB, W + 1 * 128 * 256, bl2, g2, be2, nullptr, hA);
    // layer 3: A -> out (fp32 node_embed)
    k_agg<<<warpBlocks, 256>>>(hA);
    k_layer<<<tileBlocks, 256>>>(ag, hA, W + 2 * 128 * 256, bl3, g3, be3, out, nullptr);

    k_poolA<<<BGRAPH * POOL_CH, H>>>(out);
    k_poolB<<<BGRAPH, H>>>(out);
}

// round 17
// speedup vs baseline: 1.1967x; 1.0221x over previous
#include <cuda_runtime.h>
#include <cfloat>
#include <stdint.h>

#define N_NODES 100000
#define N_EDGES 1600000
#define BGRAPH  64
#define DINP    9
#define H       128
#define EPS     1e-5f

#define SCAN_BLK 512
#define SCAN_NB  196   // ceil(100000/512)
#define POOL_CH  16
#define EMB_BLOCKS 782

typedef unsigned u32;

// ---------------- scratch (device globals; no allocation allowed) -----------
// SPLIT bf16 hi/lo storage per node: 64 u32 words each array.
// Hi word p = hi bf16 of channels (2p [lo16], 2p+1 [hi16]); Lo word p likewise.
__device__ u32 g_hAHi[N_NODES * 64];
__device__ u32 g_hALo[N_NODES * 64];
__device__ u32 g_hBHi[N_NODES * 64];
__device__ u32 g_hBLo[N_NODES * 64];
__device__ u32 g_agHi[N_NODES * 64];
__device__ u32 g_agLo[N_NODES * 64];
__device__ u32 g_W[3 * 128 * 256];      // per layer [c 128][256 words hi/lo interleaved]
__device__ int g_rowptr[N_NODES + 1];
__device__ int g_col[N_EDGES];
__device__ int g_deg[N_NODES];
__device__ int g_cursor[N_NODES];
__device__ int g_bsum[SCAN_NB];
__device__ int g_start[BGRAPH + 1];
__device__ float g_pp[BGRAPH * POOL_CH * 2 * H];

// ---------------- bf16 helpers ----------------------------------------------
__device__ __forceinline__ u32 bf16rn(float f) {
    u32 u = __float_as_uint(f);
    return (u + 0x7fffu + ((u >> 16) & 1u)) >> 16;
}
__device__ __forceinline__ void bfsplit(float f, u32& hi, u32& lo) {
    hi = bf16rn(f);
    float r = f - __uint_as_float(hi << 16);
    lo = bf16rn(r);
}

#define MMA_BF16(c0,c1,c2,c3,a0,a1,a2,a3,b0,b1) \
    asm volatile("mma.sync.aligned.m16n8k16.row.col.f32.bf16.bf16.f32 " \
        "{%0,%1,%2,%3}, {%4,%5,%6,%7}, {%8,%9}, {%0,%1,%2,%3};\n" \
        : "+f"(c0), "+f"(c1), "+f"(c2), "+f"(c3) \
        : "r"(a0), "r"(a1), "r"(a2), "r"(a3), "r"(b0), "r"(b1))

// ---------------- init: zero counters + graph starts + rowptr[N] -------------
__global__ void k_init(const int* __restrict__ batch) {
    int i = blockIdx.x * blockDim.x + threadIdx.x;
    if (i >= N_NODES) return;
    g_deg[i] = 0; g_cursor[i] = 0;
    if (i == 0) g_rowptr[N_NODES] = N_EDGES;
    int b  = batch[i];
    int bp = (i == 0) ? -1 : batch[i - 1];
    for (int g = bp + 1; g <= b; g++) g_start[g] = i;
    if (i == N_NODES - 1)
        for (int g = b + 1; g <= BGRAPH; g++) g_start[g] = N_NODES;
}

__global__ void k_deg(const int* __restrict__ dst) {
    int e = blockIdx.x * blockDim.x + threadIdx.x;
    if (e < N_EDGES) atomicAdd(&g_deg[dst[e]], 1);
}

__global__ void k_scan1() {
    __shared__ int sh[SCAN_BLK];
    int t = threadIdx.x;
    int i = blockIdx.x * SCAN_BLK + t;
    int v = (i < N_NODES) ? g_deg[i] : 0;
    sh[t] = v; __syncthreads();
    for (int o = 1; o < SCAN_BLK; o <<= 1) {
        int a = (t >= o) ? sh[t - o] : 0;
        __syncthreads();
        sh[t] += a;
        __syncthreads();
    }
    if (i < N_NODES) g_rowptr[i] = sh[t] - v;   // local exclusive
    if (t == SCAN_BLK - 1) g_bsum[blockIdx.x] = sh[t];
}

// scan3 with inline block-prefix: each block reduces bsum[0..bid-1] itself.
__global__ void k_scan3() {
    __shared__ int red[SCAN_BLK];
    int t = threadIdx.x;
    int bid = blockIdx.x;
    int v = (t < SCAN_NB && t < bid) ? g_bsum[t] : 0;
    red[t] = v; __syncthreads();
    for (int o = SCAN_BLK / 2; o > 0; o >>= 1) {
        if (t < o) red[t] += red[t + o];
        __syncthreads();
    }
    int prefix = red[0];
    int i = bid * SCAN_BLK + t;
    if (i < N_NODES) g_rowptr[i] += prefix;
}

__global__ void k_scatter(const int* __restrict__ src, const int* __restrict__ dst) {
    int e = blockIdx.x * blockDim.x + threadIdx.x;
    if (e < N_EDGES) {
        int d = dst[e];
        int p = atomicAdd(&g_cursor[d], 1);
        g_col[g_rowptr[d] + p] = src[e];
    }
}

// ---------------- weight split (interleaved): W[c][k] = [Wl ; Wr] ------------
__global__ void k_wsplit(const float* __restrict__ Wl1, const float* __restrict__ Wr1,
                         const float* __restrict__ Wl2, const float* __restrict__ Wr2,
                         const float* __restrict__ Wl3, const float* __restrict__ Wr3) {
    int idx = blockIdx.x * blockDim.x + threadIdx.x;   // pair index
    if (idx >= 3 * 128 * 128) return;
    int l = idx / (128 * 128);
    int r = idx % (128 * 128);
    int c = r >> 7;
    int kp = r & 127;
    int k0 = kp * 2;
    const float* Wl = (l == 0) ? Wl1 : (l == 1) ? Wl2 : Wl3;
    const float* Wr = (l == 0) ? Wr1 : (l == 1) ? Wr2 : Wr3;
    float w0 = (k0 < 128) ? Wl[c * 128 + k0] : Wr[c * 128 + k0 - 128];
    float w1 = (k0 + 1 < 128) ? Wl[c * 128 + k0 + 1] : Wr[c * 128 + k0 + 1 - 128];
    u32 h0, l0, h1, l1;
    bfsplit(w0, h0, l0);
    bfsplit(w1, h1, l1);
    size_t base = (size_t)l * 128 * 256 + (size_t)c * 256 + kp * 2;
    *(uint2*)&g_W[base] = make_uint2(h0 | (h1 << 16), l0 | (l1 << 16));
}

// ---------------- node embedder: register-resident W0, grid-stride ----------
__global__ void __launch_bounds__(256) k_embed(
    const float* __restrict__ x, const float* __restrict__ W0,
    const float* __restrict__ b0, const float* __restrict__ g0,
    const float* __restrict__ be0)
{
    int warpId = (blockIdx.x * blockDim.x + threadIdx.x) >> 5;
    int lane = threadIdx.x & 31;
    int nwarps = EMB_BLOCKS * 8;

    float w[4][DINP];
    float bb[4], gm[4], bt[4];
#pragma unroll
    for (int j = 0; j < 4; j++) {
        int c = lane * 4 + j;
#pragma unroll
        for (int d = 0; d < DINP; d++) w[j][d] = W0[c * DINP + d];
        bb[j] = b0[c]; gm[j] = g0[c]; bt[j] = be0[c];
    }

    for (int gw = warpId; gw < N_NODES; gw += nwarps) {
        float xd = (lane < DINP) ? __ldg(&x[gw * DINP + lane]) : 0.f;
        float xs[DINP];
#pragma unroll
        for (int d = 0; d < DINP; d++) xs[d] = __shfl_sync(0xffffffffu, xd, d);
        float o[4];
#pragma unroll
        for (int j = 0; j < 4; j++) {
            float acc = bb[j];
#pragma unroll
            for (int d = 0; d < DINP; d++) acc = fmaf(xs[d], w[j][d], acc);
            o[j] = acc;
        }
        float s1 = o[0] + o[1] + o[2] + o[3];
        float s2 = o[0]*o[0] + o[1]*o[1] + o[2]*o[2] + o[3]*o[3];
#pragma unroll
        for (int off = 16; off; off >>= 1) {
            s1 += __shfl_xor_sync(0xffffffffu, s1, off);
            s2 += __shfl_xor_sync(0xffffffffu, s2, off);
        }
        float m  = s1 * (1.f / H);
        float var = fmaxf(s2 * (1.f / H) - m * m, 0.f);
        float rs = rsqrtf(var + EPS);
        u32 hb[4], lb[4];
#pragma unroll
        for (int j = 0; j < 4; j++) {
            float v = fmaxf((o[j] - m) * rs * gm[j] + bt[j], 0.f);
            bfsplit(v, hb[j], lb[j]);
        }
        size_t base = (size_t)gw * 64 + lane * 2;
        *(uint2*)&g_hAHi[base] = make_uint2(hb[0] | (hb[1] << 16), hb[2] | (hb[3] << 16));
        *(uint2*)&g_hALo[base] = make_uint2(lb[0] | (lb[1] << 16), lb[2] | (lb[3] << 16));
    }
}

// ---------------- mean aggregation: warp per node, HI-ONLY gather ------------
// Neighbor values read as plain bf16 (hi); lo dropped (error ~2^-9/value, which
// contracts through the 128-wide GEMM to ~1e-4 at output). Halves gather bytes.
__global__ void k_agg(const u32* __restrict__ hHi) {
    int gw = (blockIdx.x * blockDim.x + threadIdx.x) >> 5;
    int lane = threadIdx.x & 31;
    if (gw >= N_NODES) return;
    int s = g_rowptr[gw], e = g_rowptr[gw + 1];
    int lane2 = lane * 2;
    float a0 = 0.f, a1 = 0.f, a2 = 0.f, a3 = 0.f;
    float b0 = 0.f, b1 = 0.f, b2 = 0.f, b3 = 0.f;
    int p = s;
    for (; p + 1 < e; p += 2) {
        int sn0 = __ldg(&g_col[p]);
        int sn1 = __ldg(&g_col[p + 1]);
        uint2 w0 = *(const uint2*)&hHi[(size_t)sn0 * 64 + lane2];
        uint2 w1 = *(const uint2*)&hHi[(size_t)sn1 * 64 + lane2];
        a0 += __uint_as_float(w0.x << 16);
        a1 += __uint_as_float(w0.x & 0xffff0000u);
        a2 += __uint_as_float(w0.y << 16);
        a3 += __uint_as_float(w0.y & 0xffff0000u);
        b0 += __uint_as_float(w1.x << 16);
        b1 += __uint_as_float(w1.x & 0xffff0000u);
        b2 += __uint_as_float(w1.y << 16);
        b3 += __uint_as_float(w1.y & 0xffff0000u);
    }
    if (p < e) {
        int sn = __ldg(&g_col[p]);
        uint2 w = *(const uint2*)&hHi[(size_t)sn * 64 + lane2];
        a0 += __uint_as_float(w.x << 16);
        a1 += __uint_as_float(w.x & 0xffff0000u);
        a2 += __uint_as_float(w.y << 16);
        a3 += __uint_as_float(w.y & 0xffff0000u);
    }
    float inv = 1.f / fmaxf((float)(e - s), 1.f);
    a0 = (a0 + b0) * inv; a1 = (a1 + b1) * inv;
    a2 = (a2 + b2) * inv; a3 = (a3 + b3) * inv;
    u32 h0, l0, h1, l1, h2, l2, h3, l3;
    bfsplit(a0, h0, l0); bfsplit(a1, h1, l1);
    bfsplit(a2, h2, l2); bfsplit(a3, h3, l3);
    size_t base = (size_t)gw * 64 + lane2;
    *(uint2*)&g_agHi[base] = make_uint2(h0 | (h1 << 16), h2 | (h3 << 16));
    *(uint2*)&g_agLo[base] = make_uint2(l0 | (l1 << 16), l2 | (l3 << 16));
}

// ---------------- tensor-core layer: bf16x3 MMA + LayerNorm + ReLU ----------
__global__ void __launch_bounds__(256, 2) k_layer(
    const u32* __restrict__ agHi, const u32* __restrict__ agLo,
    const u32* __restrict__ hHi,  const u32* __restrict__ hLo,
    const u32* __restrict__ W,
    const float* __restrict__ bl, const float* __restrict__ gg,
    const float* __restrict__ be,
    float* __restrict__ outF, u32* __restrict__ outHi, u32* __restrict__ outLo)
{
    __shared__ __align__(16) u32 AsHi[128 * 16];
    __shared__ __align__(16) u32 AsLo[128 * 16];
    __shared__ __align__(16) u32 WsHi[128 * 16];
    __shared__ __align__(16) u32 WsLo[128 * 16];
    __shared__ float sBl[128], sGg[128], sBe[128];

    int t = threadIdx.x;
    int lane = t & 31;
    int wid = t >> 5;
    int g  = lane >> 2;
    int t2 = lane & 3;
    int m0 = wid * 16;
    int nodeBase = blockIdx.x * 128;

    if (t < 128) { sBl[t] = bl[t]; sGg[t] = gg[t]; sBe[t] = be[t]; }

    int sRow[8], sJ32[8], sIdx[8];
#pragma unroll
    for (int it = 0; it < 8; it++) {
        int i = it * 256 + t;
        int row = i >> 4;
        int j32 = i & 15;
        int blk = j32 >> 3, j = j32 & 7;
        int pj = (j < 4) ? (2 * j) : (2 * j - 7);
        sRow[it] = row;
        sJ32[it] = j32;
        sIdx[it] = (row * 16 + blk * 8 + pj) ^ (((row >> 1) & 1) << 3);
    }

    float acc[16][4];
#pragma unroll
    for (int nt = 0; nt < 16; nt++)
#pragma unroll
        for (int j = 0; j < 4; j++) acc[nt][j] = 0.f;

    // ---- prologue: stage chunk 0 (from ag) ----
#pragma unroll
    for (int it = 0; it < 8; it++) {
        int gnode = nodeBase + sRow[it];
        u32 vh = 0u, vl = 0u;
        if (gnode < N_NODES) {
            size_t fi = (size_t)gnode * 64 + sJ32[it];
            vh = agHi[fi]; vl = agLo[fi];
        }
        AsHi[sIdx[it]] = vh; AsLo[sIdx[it]] = vl;
        uint2 w = *(const uint2*)&W[(size_t)sRow[it] * 256 + 2 * sJ32[it]];
        WsHi[sIdx[it]] = w.x; WsLo[sIdx[it]] = w.y;
    }
    __syncthreads();

#pragma unroll 1
    for (int kk = 0; kk < 256; kk += 32) {
        u32 vah[8], val[8];
        uint2 vw[8];
        bool have = (kk + 32) < 256;
        if (have) {
            int kn = kk + 32;
            const u32* fHi = (kn < 128) ? agHi : hHi;
            const u32* fLo = (kn < 128) ? agLo : hLo;
            int koffp = ((kn < 128) ? kn : kn - 128) >> 1;
#pragma unroll
            for (int it = 0; it < 8; it++) {
                int gnode = nodeBase + sRow[it];
                vah[it] = 0u; val[it] = 0u;
                if (gnode < N_NODES) {
                    size_t fi = (size_t)gnode * 64 + koffp + sJ32[it];
                    vah[it] = fHi[fi]; val[it] = fLo[fi];
                }
                vw[it] = *(const uint2*)&W[(size_t)sRow[it] * 256 + kn + 2 * sJ32[it]];
            }
        }

#pragma unroll
        for (int blk = 0; blk < 2; blk++) {
            int rA = m0 + g, rB = m0 + g + 8;
            int iA = (rA * 16 + blk * 8 + 2 * t2) ^ (((rA >> 1) & 1) << 3);
            int iB = (rB * 16 + blk * 8 + 2 * t2) ^ (((rB >> 1) & 1) << 3);
            uint2 a02h = *(const uint2*)&AsHi[iA];
            uint2 a13h = *(const uint2*)&AsHi[iB];
            uint2 a02l = *(const uint2*)&AsLo[iA];
            uint2 a13l = *(const uint2*)&AsLo[iB];
#pragma unroll
            for (int nt = 0; nt < 16; nt++) {
                int c = nt * 8 + g;
                int iW = (c * 16 + blk * 8 + 2 * t2) ^ (((c >> 1) & 1) << 3);
                uint2 bh = *(const uint2*)&WsHi[iW];
                uint2 blo = *(const uint2*)&WsLo[iW];
                MMA_BF16(acc[nt][0], acc[nt][1], acc[nt][2], acc[nt][3],
                         a02h.x, a13h.x, a02h.y, a13h.y, bh.x, bh.y);
                MMA_BF16(acc[nt][0], acc[nt][1], acc[nt][2], acc[nt][3],
                         a02h.x, a13h.x, a02h.y, a13h.y, blo.x, blo.y);
                MMA_BF16(acc[nt][0], acc[nt][1], acc[nt][2], acc[nt][3],
                         a02l.x, a13l.x, a02l.y, a13l.y, bh.x, bh.y);
            }
        }
        __syncthreads();
        if (have) {
#pragma unroll
            for (int it = 0; it < 8; it++) {
                AsHi[sIdx[it]] = vah[it]; AsLo[sIdx[it]] = val[it];
                WsHi[sIdx[it]] = vw[it].x; WsLo[sIdx[it]] = vw[it].y;
            }
            __syncthreads();
        }
    }

    // ---- epilogue ----
    float sA1 = 0.f, sA2 = 0.f, sB1 = 0.f, sB2 = 0.f;
#pragma unroll
    for (int nt = 0; nt < 16; nt++) {
        int c0 = nt * 8 + 2 * t2;
        float b0 = sBl[c0], b1 = sBl[c0 + 1];
        float va0 = acc[nt][0] + b0, va1 = acc[nt][1] + b1;
        float vb0 = acc[nt][2] + b0, vb1 = acc[nt][3] + b1;
        sA1 += va0 + va1; sA2 += va0 * va0 + va1 * va1;
        sB1 += vb0 + vb1; sB2 += vb0 * vb0 + vb1 * vb1;
    }
#pragma unroll
    for (int off = 1; off <= 2; off <<= 1) {
        sA1 += __shfl_xor_sync(0xffffffffu, sA1, off);
        sA2 += __shfl_xor_sync(0xffffffffu, sA2, off);
        sB1 += __shfl_xor_sync(0xffffffffu, sB1, off);
        sB2 += __shfl_xor_sync(0xffffffffu, sB2, off);
    }
    float mA = sA1 * (1.f / H);
    float vA = fmaxf(sA2 * (1.f / H) - mA * mA, 0.f);
    float rsA = rsqrtf(vA + EPS);
    float mB = sB1 * (1.f / H);
    float vB = fmaxf(sB2 * (1.f / H) - mB * mB, 0.f);
    float rsB = rsqrtf(vB + EPS);

    int gA = nodeBase + m0 + g;
    int gB = gA + 8;
    bool wA = gA < N_NODES, wB = gB < N_NODES;

#pragma unroll
    for (int nt = 0; nt < 16; nt++) {
        int c0 = nt * 8 + 2 * t2;
        float b0 = sBl[c0], b1 = sBl[c0 + 1];
        float gg0 = sGg[c0], gg1 = sGg[c0 + 1];
        float be0 = sBe[c0], be1 = sBe[c0 + 1];
        float oa0 = fmaxf((acc[nt][0] + b0 - mA) * rsA * gg0 + be0, 0.f);
        float oa1 = fmaxf((acc[nt][1] + b1 - mA) * rsA * gg1 + be1, 0.f);
        float ob0 = fmaxf((acc[nt][2] + b0 - mB) * rsB * gg0 + be0, 0.f);
        float ob1 = fmaxf((acc[nt][3] + b1 - mB) * rsB * gg1 + be1, 0.f);
        if (outF) {
            if (wA) *(float2*)&outF[(size_t)gA * 128 + c0] = make_float2(oa0, oa1);
            if (wB) *(float2*)&outF[(size_t)gB * 128 + c0] = make_float2(ob0, ob1);
        } else {
            u32 h0, l0, h1, l1;
            int pi = nt * 4 + t2;   // pair index = c0/2
            if (wA) {
                bfsplit(oa0, h0, l0); bfsplit(oa1, h1, l1);
                outHi[(size_t)gA * 64 + pi] = h0 | (h1 << 16);
                outLo[(size_t)gA * 64 + pi] = l0 | (l1 << 16);
            }
            if (wB) {
                bfsplit(ob0, h0, l0); bfsplit(ob1, h1, l1);
                outHi[(size_t)gB * 64 + pi] = h0 | (h1 << 16);
                outLo[(size_t)gB * 64 + pi] = l0 | (l1 << 16);
            }
        }
    }
}

// ---------------- pooling (two-stage) ---------------------------------------
__global__ void k_poolA(const float* __restrict__ ne) {
    int b  = blockIdx.x / POOL_CH;
    int ch = blockIdx.x % POOL_CH;
    int c  = threadIdx.x;
    int s = g_start[b], e = g_start[b + 1];
    int len = e - s;
    int cs = s + (int)(((long long)len * ch) / POOL_CH);
    int ce = s + (int)(((long long)len * (ch + 1)) / POOL_CH);
    float sum = 0.f, mx = -FLT_MAX;
    for (int n = cs; n < ce; n++) {
        float v = ne[(size_t)n * H + c];
        sum += v;
        mx = fmaxf(mx, v);
    }
    size_t base = ((size_t)(b * POOL_CH + ch)) * 2 * H;
    g_pp[base + c]     = sum;
    g_pp[base + H + c] = mx;
}

__global__ void k_poolB(float* __restrict__ out) {
    int b = blockIdx.x;
    int c = threadIdx.x;
    int s = g_start[b], e = g_start[b + 1];
    float sum = 0.f, mx = -FLT_MAX;
#pragma unroll
    for (int ch = 0; ch < POOL_CH; ch++) {
        size_t base = ((size_t)(b * POOL_CH + ch)) * 2 * H;
        sum += g_pp[base + c];
        mx = fmaxf(mx, g_pp[base + H + c]);
    }
    float cnt = (float)(e - s);
    size_t gbase = (size_t)N_NODES * H + (size_t)b * 2 * H;
    out[gbase + c]     = sum / fmaxf(cnt, 1.f);
    out[gbase + H + c] = mx;
}

// ---------------- launch ----------------------------------------------------
extern "C" void kernel_launch(void* const* d_in, const int* in_sizes, int n_in,
                              void* d_out, int out_size) {
    const float* x     = (const float*)d_in[0];
    const int*   ei    = (const int*)  d_in[1];
    const int*   batch = (const int*)  d_in[2];
    const float* W0  = (const float*)d_in[3];
    const float* b0  = (const float*)d_in[4];
    const float* g0  = (const float*)d_in[5];
    const float* be0 = (const float*)d_in[6];
    const float* Wl1 = (const float*)d_in[7];
    const float* bl1 = (const float*)d_in[8];
    const float* Wr1 = (const float*)d_in[9];
    const float* g1  = (const float*)d_in[10];
    const float* be1 = (const float*)d_in[11];
    const float* Wl2 = (const float*)d_in[12];
    const float* bl2 = (const float*)d_in[13];
    const float* Wr2 = (const float*)d_in[14];
    const float* g2  = (const float*)d_in[15];
    const float* be2 = (const float*)d_in[16];
    const float* Wl3 = (const float*)d_in[17];
    const float* bl3 = (const float*)d_in[18];
    const float* Wr3 = (const float*)d_in[19];
    const float* g3  = (const float*)d_in[20];
    const float* be3 = (const float*)d_in[21];

    const int* src = ei;
    const int* dst = ei + N_EDGES;
    float* out = (float*)d_out;

    u32 *hAHi, *hALo, *hBHi, *hBLo, *agHi, *agLo, *W;
    cudaGetSymbolAddress((void**)&hAHi, g_hAHi);
    cudaGetSymbolAddress((void**)&hALo, g_hALo);
    cudaGetSymbolAddress((void**)&hBHi, g_hBHi);
    cudaGetSymbolAddress((void**)&hBLo, g_hBLo);
    cudaGetSymbolAddress((void**)&agHi, g_agHi);
    cudaGetSymbolAddress((void**)&agLo, g_agLo);
    cudaGetSymbolAddress((void**)&W, g_W);

    const int nodeBlocks = (N_NODES + 255) / 256;
    const int edgeBlocks = (N_EDGES + 255) / 256;
    const int warpBlocks = (N_NODES + 7) / 8;          // 8 warps/block
    const int tileBlocks = (N_NODES + 127) / 128;      // 782

    // CSR build (every launch — caching is forbidden)
    k_init<<<nodeBlocks, 256>>>(batch);
    k_deg<<<edgeBlocks, 256>>>(dst);
    k_scan1<<<SCAN_NB, SCAN_BLK>>>();
    k_scan3<<<SCAN_NB, SCAN_BLK>>>();
    k_scatter<<<edgeBlocks, 256>>>(src, dst);

    k_wsplit<<<(3 * 128 * 128 + 255) / 256, 256>>>(Wl1, Wr1, Wl2, Wr2, Wl3, Wr3);
    k_embed<<<EMB_BLOCKS, 256>>>(x, W0, b0, g0, be0);

    // layer 1: A -> B
    k_agg<<<warpBlocks, 256>>>(hAHi);
    k_layer<<<tileBlocks, 256>>>(agHi, agLo, hAHi, hALo, W + 0 * 128 * 256,
                                 bl1, g1, be1, nullptr, hBHi, hBLo);
    // layer 2: B -> A
    k_agg<<<warpBlocks, 256>>>(hBHi);
    k_layer<<<tileBlocks, 256>>>(agHi, agLo, hBHi, hBLo, W + 1 * 128 * 256,
                                 bl2, g2, be2, nullptr, hAHi, hALo);
    // layer 3: A -> out (fp32 node_embed)
    k_agg<<<warpBlocks, 256>>>(hAHi);
    k_layer<<<tileBlocks, 256>>>(agHi, agLo, hAHi, hALo, W + 2 * 128 * 256,
                                 bl3, g3, be3, out, nullptr, nullptr);

    k_poolA<<<BGRAPH * POOL_CH, H>>>(out);
    k_poolB<<<BGRAPH, H>>>(out);
}